// round 7
// baseline (speedup 1.0000x reference)
#include <cuda_runtime.h>

// ---------------- problem constants ---------------------------------------
#define Hdim   128
#define Odim   32
#define INdim  64
#define RB     8           // init kernel rows per block
#define RB2    16          // node/combine rows per block
#define NTHR   128
#define NTHR2  384         // 3 warpgroups (one per gate)
#define MAXB   16384
#define MAXLVL 6

// ---------------- static device scratch -----------------------------------
__device__ float g_H0 [(size_t)MAXB * Hdim];
__device__ float g_HAI[(size_t)MAXLVL * MAXB * Hdim];
__device__ float g_H2 [(size_t)MAXLVL * MAXB * Hdim];
__device__ float g_PR [(size_t)(MAXLVL + 1) * MAXB * Odim];

// packed weights: [gate][k4][j][4] per matrix
#define OFF_WH_A 0
#define OFF_WI_A 49152
#define OFF_WH_F 61440
#define OFF_WI_F 110592
#define OFF_UF   122880
#define OFF_UA   139264
__device__ float g_WP[155648];

typedef unsigned long long u64;
union F4U { float4 f; ulonglong2 u; };

__device__ __forceinline__ void ffma2(u64& d, u64 a, u64 b) {
    asm volatile("fma.rn.f32x2 %0, %1, %2, %0;" : "+l"(d) : "l"(a), "l"(b));
}
__device__ __forceinline__ u64 pack2(float lo, float hi) {
    u64 r; asm("mov.b64 %0, {%1, %2};" : "=l"(r) : "f"(lo), "f"(hi)); return r;
}
__device__ __forceinline__ float f2sum(u64 v) {
    float lo, hi; asm("mov.b64 {%0, %1}, %2;" : "=f"(lo), "=f"(hi) : "l"(v));
    return lo + hi;
}
__device__ __forceinline__ float sigmoidf_(float x) {
    return 1.0f / (1.0f + expf(-x));
}

// ---------------- weight repack prologue ----------------------------------
__device__ __forceinline__ void pack_one(const float* __restrict__ src,
                                         float* __restrict__ dst, int g) {
    int k4 = g >> 7, j = g & 127;
    float4 v;
    v.x = src[(size_t)(4 * k4 + 0) * 128 + j];
    v.y = src[(size_t)(4 * k4 + 1) * 128 + j];
    v.z = src[(size_t)(4 * k4 + 2) * 128 + j];
    v.w = src[(size_t)(4 * k4 + 3) * 128 + j];
    *reinterpret_cast<float4*>(dst + (size_t)g * 4) = v;
}

__global__ void pack_kernel(const float* __restrict__ awh, const float* __restrict__ awi,
                            const float* __restrict__ fwh, const float* __restrict__ fwi,
                            const float* __restrict__ ufw, const float* __restrict__ uaw,
                            float* __restrict__ WP) {
    int g = blockIdx.x * blockDim.x + threadIdx.x;
    if      (g < 12288) pack_one(awh, WP + OFF_WH_A, g);
    else if (g < 15360) pack_one(awi, WP + OFF_WI_A, g - 12288);
    else if (g < 27648) pack_one(fwh, WP + OFF_WH_F, g - 15360);
    else if (g < 30720) pack_one(fwi, WP + OFF_WI_F, g - 27648);
    else if (g < 34816) pack_one(ufw, WP + OFF_UF,   g - 30720);
    else if (g < 38912) pack_one(uaw, WP + OFF_UA,   g - 34816);
}

// ---------------- init: hidden = z @ z2h_w + z2h_b ------------------------
__global__ void __launch_bounds__(NTHR)
init_kernel(const float* __restrict__ z, const float* __restrict__ w,
            const float* __restrict__ b, float* __restrict__ hout) {
    __shared__ float zs[RB][INdim];
    const int j    = threadIdx.x;
    const int row0 = blockIdx.x * RB;

    {
        const float4* src = reinterpret_cast<const float4*>(z + (size_t)row0 * INdim);
        float4* dst = reinterpret_cast<float4*>(&zs[0][0]);
        for (int i = j; i < RB * INdim / 4; i += NTHR) dst[i] = src[i];
    }
    __syncthreads();

    const float bb = b[j];
    float acc[RB];
#pragma unroll
    for (int i = 0; i < RB; i++) acc[i] = bb;
#pragma unroll 4
    for (int k = 0; k < INdim; k += 4) {
        float4 hv[RB];
#pragma unroll
        for (int i = 0; i < RB; i++)
            hv[i] = *reinterpret_cast<const float4*>(&zs[i][k]);
#pragma unroll
        for (int kk = 0; kk < 4; kk++) {
            float wv = w[(size_t)(k + kk) * Hdim + j];
#pragma unroll
            for (int i = 0; i < RB; i++) {
                float h = (kk == 0) ? hv[i].x : (kk == 1) ? hv[i].y
                          : (kk == 2) ? hv[i].z : hv[i].w;
                acc[i] += h * wv;
            }
        }
    }
#pragma unroll
    for (int i = 0; i < RB; i++)
        hout[(size_t)(row0 + i) * Hdim + j] = acc[i];
}

// ---------------- shared accumulation core ---------------------------------
// acc[16] over nk4 k-groups; pact row stride in ulonglong2 units; 8-row halves
// bound register pressure (weights reused across both halves).
__device__ __forceinline__ void accum_k(u64* acc, const float4* __restrict__ pw,
                                        int nk4, const ulonglong2* __restrict__ pact,
                                        int rowStride) {
#pragma unroll 4
    for (int k4 = 0; k4 < nk4; k4++) {
        F4U w; w.f = pw[k4 * 128];
#pragma unroll
        for (int half = 0; half < 2; half++) {
            ulonglong2 a[8];
#pragma unroll
            for (int i = 0; i < 8; i++)
                a[i] = pact[(half * 8 + i) * rowStride + k4];
#pragma unroll
            for (int i = 0; i < 8; i++) {
                ffma2(acc[half * 8 + i], a[i].x, w.u.x);
                ffma2(acc[half * 8 + i], a[i].y, w.u.y);
            }
        }
    }
}

// ---------------- fused node kernel (gate-split warpgroups) ----------------
__global__ void __launch_bounds__(NTHR2, 2)
node_kernel(const float* __restrict__ h_a,
            const float* __restrict__ h2o_w, const float* __restrict__ h2o_b,
            const float* __restrict__ wiP,   const float* __restrict__ bi,
            const float* __restrict__ whP,   const float* __restrict__ bh,
            float* __restrict__ pred_out, float* __restrict__ probs_out,
            float* __restrict__ h_out) {
    __shared__ float hs[RB2 * Hdim];
    __shared__ float ps[RB2 * Odim];
    __shared__ float gR[RB2 * Hdim];
    __shared__ float gZ[RB2 * Hdim];
    __shared__ float xn[RB2 * Hdim];
    const int t    = threadIdx.x;
    const int row0 = blockIdx.x * RB2;

    {
        const float4* src = reinterpret_cast<const float4*>(h_a + (size_t)row0 * Hdim);
        float4* dst = reinterpret_cast<float4*>(hs);
        for (int i = t; i < RB2 * Hdim / 4; i += NTHR2) dst[i] = src[i];
    }
    __syncthreads();

    // ---- pred + softmax: warps 0..7, warp w -> rows 2w, 2w+1; lane = o ----
    {
        const int o = t & 31, w = t >> 5;
        if (w < 8) {
            float acc[2];
            const float bb = h2o_b[o];
            acc[0] = bb; acc[1] = bb;
#pragma unroll 4
            for (int k = 0; k < Hdim; k += 4) {
                float4 h0 = *reinterpret_cast<const float4*>(&hs[(w * 2 + 0) * Hdim + k]);
                float4 h1 = *reinterpret_cast<const float4*>(&hs[(w * 2 + 1) * Hdim + k]);
#pragma unroll
                for (int kk = 0; kk < 4; kk++) {
                    float wv = h2o_w[(size_t)(k + kk) * Odim + o];
                    float a0 = (kk == 0) ? h0.x : (kk == 1) ? h0.y : (kk == 2) ? h0.z : h0.w;
                    float a1 = (kk == 0) ? h1.x : (kk == 1) ? h1.y : (kk == 2) ? h1.z : h1.w;
                    acc[0] += a0 * wv;
                    acc[1] += a1 * wv;
                }
            }
#pragma unroll
            for (int i = 0; i < 2; i++) {
                int r = w * 2 + i;
                float v = acc[i];
                pred_out[(size_t)(row0 + r) * Odim + o] = v;
                float m = v;
#pragma unroll
                for (int s = 16; s > 0; s >>= 1)
                    m = fmaxf(m, __shfl_xor_sync(0xffffffffu, m, s));
                float e = expf(v - m);
                float ssum = e;
#pragma unroll
                for (int s = 16; s > 0; s >>= 1)
                    ssum += __shfl_xor_sync(0xffffffffu, ssum, s);
                float p = e / ssum;
                ps[r * Odim + o] = p;
                probs_out[(size_t)(row0 + r) * Odim + o] = p;
            }
        }
    }
    __syncthreads();

    // ---- gate accumulation: warpgroup g owns gate g ----
    const int j = t & 127, g = t >> 7;
    const float4* pw  = reinterpret_cast<const float4*>(whP) + g * 4096 + j;
    const float4* pwi = reinterpret_cast<const float4*>(wiP) + g * 1024 + j;
    const ulonglong2* ph = reinterpret_cast<const ulonglong2*>(hs);  // stride 32
    const ulonglong2* pp = reinterpret_cast<const ulonglong2*>(ps);  // stride 8

    u64 acc[RB2];
    if (g < 2) {
        const float b0 = bi[g * Hdim + j] + bh[g * Hdim + j];
#pragma unroll
        for (int i = 0; i < RB2; i++) acc[i] = pack2(b0, 0.0f);
        accum_k(acc, pwi, Odim / 4, pp, 8);
        accum_k(acc, pw,  Hdim / 4, ph, 32);
        float* dstg = (g == 0) ? gR : gZ;
#pragma unroll
        for (int i = 0; i < RB2; i++)
            dstg[i * Hdim + j] = sigmoidf_(f2sum(acc[i]));
    } else {
        const float bx = bi[2 * Hdim + j];
#pragma unroll
        for (int i = 0; i < RB2; i++) acc[i] = pack2(bx, 0.0f);
        accum_k(acc, pwi, Odim / 4, pp, 8);
#pragma unroll
        for (int i = 0; i < RB2; i++)
            xn[i * Hdim + j] = f2sum(acc[i]);
        const float bh2 = bh[2 * Hdim + j];
#pragma unroll
        for (int i = 0; i < RB2; i++) acc[i] = pack2(bh2, 0.0f);
        accum_k(acc, pw, Hdim / 4, ph, 32);
    }
    __syncthreads();

    if (g == 2) {
        float* po = h_out + (size_t)row0 * Hdim + j;
#pragma unroll
        for (int i = 0; i < RB2; i++) {
            float rg = gR[i * Hdim + j];
            float zg = gZ[i * Hdim + j];
            float n  = tanhf(xn[i * Hdim + j] + rg * f2sum(acc[i]));
            float hv = hs[i * Hdim + j];
            po[i * Hdim] = (1.0f - zg) * n + zg * hv;
        }
    }
}

// ---------------- fused combine kernel (gate-split + merge) ----------------
__global__ void __launch_bounds__(NTHR2, 2)
combine_kernel(const float* __restrict__ probs_fc,
               const float* __restrict__ h_ai, const float* __restrict__ h_a,
               const float* __restrict__ wiP,  const float* __restrict__ bi,
               const float* __restrict__ whP,  const float* __restrict__ bh,
               const float* __restrict__ ufP,  const float* __restrict__ ufb,
               const float* __restrict__ uaP,  const float* __restrict__ uab,
               float* __restrict__ h2_out) {
    __shared__ float hs[RB2 * Hdim];   // h_ai, later h_a
    __shared__ float ps[RB2 * Odim];
    __shared__ float gR[RB2 * Hdim];
    __shared__ float gZ[RB2 * Hdim];
    __shared__ float xn[RB2 * Hdim];
    __shared__ float hf[RB2 * Hdim];
    const int t    = threadIdx.x;
    const int row0 = blockIdx.x * RB2;

    {
        const float4* src = reinterpret_cast<const float4*>(h_ai + (size_t)row0 * Hdim);
        float4* dst = reinterpret_cast<float4*>(hs);
        for (int i = t; i < RB2 * Hdim / 4; i += NTHR2) dst[i] = src[i];
        const float4* psrc = reinterpret_cast<const float4*>(probs_fc + (size_t)row0 * Odim);
        float4* pdst = reinterpret_cast<float4*>(ps);
        if (t < RB2 * Odim / 4) pdst[t] = psrc[t];
    }
    __syncthreads();

    const int j = t & 127, g = t >> 7;
    const float4* pw  = reinterpret_cast<const float4*>(whP) + g * 4096 + j;
    const float4* pwi = reinterpret_cast<const float4*>(wiP) + g * 1024 + j;
    const ulonglong2* ph = reinterpret_cast<const ulonglong2*>(hs);
    const ulonglong2* pp = reinterpret_cast<const ulonglong2*>(ps);

    u64 acc[RB2];
    if (g < 2) {
        const float b0 = bi[g * Hdim + j] + bh[g * Hdim + j];
#pragma unroll
        for (int i = 0; i < RB2; i++) acc[i] = pack2(b0, 0.0f);
        accum_k(acc, pwi, Odim / 4, pp, 8);
        accum_k(acc, pw,  Hdim / 4, ph, 32);
        float* dstg = (g == 0) ? gR : gZ;
#pragma unroll
        for (int i = 0; i < RB2; i++)
            dstg[i * Hdim + j] = sigmoidf_(f2sum(acc[i]));
    } else {
        const float bx = bi[2 * Hdim + j];
#pragma unroll
        for (int i = 0; i < RB2; i++) acc[i] = pack2(bx, 0.0f);
        accum_k(acc, pwi, Odim / 4, pp, 8);
#pragma unroll
        for (int i = 0; i < RB2; i++)
            xn[i * Hdim + j] = f2sum(acc[i]);
        const float bh2 = bh[2 * Hdim + j];
#pragma unroll
        for (int i = 0; i < RB2; i++) acc[i] = pack2(bh2, 0.0f);
        accum_k(acc, pw, Hdim / 4, ph, 32);
    }
    __syncthreads();

    if (g == 2) {
#pragma unroll
        for (int i = 0; i < RB2; i++) {
            float rg = gR[i * Hdim + j];
            float zg = gZ[i * Hdim + j];
            float n  = tanhf(xn[i * Hdim + j] + rg * f2sum(acc[i]));
            float hv = hs[i * Hdim + j];
            hf[i * Hdim + j] = (1.0f - zg) * n + zg * hv;
        }
    }
    __syncthreads();
    // reload hs with h_a
    {
        const float4* src = reinterpret_cast<const float4*>(h_a + (size_t)row0 * Hdim);
        float4* dst = reinterpret_cast<float4*>(hs);
        for (int i = t; i < RB2 * Hdim / 4; i += NTHR2) dst[i] = src[i];
    }
    __syncthreads();

    // merge: h2 = tanh(hf@ufw + hs@uaw + ufb + uab); warpgroup g -> row slice
    {
        const int r0 = g * 6;
        const int nr = (g < 2) ? 6 : 4;              // rows 0-5 / 6-11 / 12-15
        const float bb = ufb[j] + uab[j];
        u64 macc[6];
#pragma unroll
        for (int i = 0; i < 6; i++) macc[i] = pack2(bb, 0.0f);

        const float4* pf = reinterpret_cast<const float4*>(ufP) + j;
        const float4* pa = reinterpret_cast<const float4*>(uaP) + j;
        const ulonglong2* phf = reinterpret_cast<const ulonglong2*>(hf);
        const ulonglong2* phs = reinterpret_cast<const ulonglong2*>(hs);
#pragma unroll 4
        for (int k4 = 0; k4 < Hdim / 4; k4++) {
            F4U wf, wa;
            wf.f = pf[k4 * 128];
            wa.f = pa[k4 * 128];
#pragma unroll
            for (int i = 0; i < 6; i++) {
                if (i < nr) {
                    ulonglong2 hv = phf[(r0 + i) * 32 + k4];
                    ulonglong2 av = phs[(r0 + i) * 32 + k4];
                    ffma2(macc[i], hv.x, wf.u.x); ffma2(macc[i], hv.y, wf.u.y);
                    ffma2(macc[i], av.x, wa.u.x); ffma2(macc[i], av.y, wa.u.y);
                }
            }
        }
        float* po = h2_out + (size_t)(row0 + r0) * Hdim + j;
#pragma unroll
        for (int i = 0; i < 6; i++)
            if (i < nr) po[i * Hdim] = tanhf(f2sum(macc[i]));
    }
}

// ---------------- host-side tree orchestration (single stream) ------------
struct EmitCtx {
    const float *h2o_w, *h2o_b;
    const float *abi, *abh, *fbi, *fbh;
    const float *uab, *ufb;
    const float *awiP, *awhP, *fwiP, *fwhP, *ufP, *uaP;
    float* out;
    float *HAI, *H2, *PR;
    int B, grid, idx;
};

static void emit_node(EmitCtx& P, int lvl, int d, const float* h_in) {
    float* probs = P.PR  + (size_t)lvl * P.B * Odim;
    float* h_ai  = P.HAI + (size_t)lvl * P.B * Hdim;
    node_kernel<<<P.grid, NTHR2>>>(h_in, P.h2o_w, P.h2o_b,
                                   P.awiP, P.abi, P.awhP, P.abh,
                                   P.out + (size_t)P.idx * P.B * Odim,
                                   probs, h_ai);
    P.idx++;
    if (d > 0) {
        emit_node(P, lvl + 1, d - 1, h_ai);
        float* h2 = P.H2 + (size_t)lvl * P.B * Hdim;
        combine_kernel<<<P.grid, NTHR2>>>(P.PR + (size_t)(lvl + 1) * P.B * Odim,
                                          h_ai, h_in,
                                          P.fwiP, P.fbi, P.fwhP, P.fbh,
                                          P.ufP, P.ufb, P.uaP, P.uab, h2);
        emit_node(P, lvl + 1, d - 1, h2);
    }
}

extern "C" void kernel_launch(void* const* d_in, const int* in_sizes, int n_in,
                              void* d_out, int out_size) {
    const float* z      = (const float*)d_in[0];
    const float* z2h_w  = (const float*)d_in[1];
    const float* z2h_b  = (const float*)d_in[2];
    const float* h2o_w  = (const float*)d_in[3];
    const float* h2o_b  = (const float*)d_in[4];
    const float* awi    = (const float*)d_in[5];
    const float* abi    = (const float*)d_in[6];
    const float* awh    = (const float*)d_in[7];
    const float* abh    = (const float*)d_in[8];
    const float* fwi    = (const float*)d_in[9];
    const float* fbi    = (const float*)d_in[10];
    const float* fwh    = (const float*)d_in[11];
    const float* fbh    = (const float*)d_in[12];
    const float* uaw    = (const float*)d_in[13];
    const float* uab    = (const float*)d_in[14];
    const float* ufw    = (const float*)d_in[15];
    const float* ufb    = (const float*)d_in[16];

    const int H  = in_sizes[2];               // 128
    const int O  = in_sizes[4];               // 32
    const int IN = in_sizes[1] / H;           // 64
    const int B  = in_sizes[0] / IN;          // 16384
    const int nn = out_size / (B * O);        // tree nodes (31)
    int depth = 0;
    while (((2 << depth) - 1) < nn) depth++;

    float *H0p, *HAIp, *H2p, *PRp, *WPp;
    cudaGetSymbolAddress((void**)&H0p,  g_H0);
    cudaGetSymbolAddress((void**)&HAIp, g_HAI);
    cudaGetSymbolAddress((void**)&H2p,  g_H2);
    cudaGetSymbolAddress((void**)&PRp,  g_PR);
    cudaGetSymbolAddress((void**)&WPp,  g_WP);

    pack_kernel<<<(38912 + 255) / 256, 256>>>(awh, awi, fwh, fwi, ufw, uaw, WPp);
    init_kernel<<<B / RB, NTHR>>>(z, z2h_w, z2h_b, H0p);

    EmitCtx P;
    P.h2o_w = h2o_w; P.h2o_b = h2o_b;
    P.abi = abi; P.abh = abh; P.fbi = fbi; P.fbh = fbh;
    P.uab = uab; P.ufb = ufb;
    P.awiP = WPp + OFF_WI_A; P.awhP = WPp + OFF_WH_A;
    P.fwiP = WPp + OFF_WI_F; P.fwhP = WPp + OFF_WH_F;
    P.ufP  = WPp + OFF_UF;   P.uaP  = WPp + OFF_UA;
    P.out  = (float*)d_out;
    P.HAI = HAIp; P.H2 = H2p; P.PR = PRp;
    P.B = B; P.grid = B / RB2; P.idx = 0;

    emit_node(P, 0, depth, H0p);
}

// round 8
// speedup vs baseline: 1.0002x; 1.0002x over previous
#include <cuda_runtime.h>

// ---------------- problem constants ---------------------------------------
#define Hdim   128
#define Odim   32
#define INdim  64
#define RB     8           // init kernel rows per block
#define RB2    16          // node/combine rows per block
#define NTHR   128
#define NTHR2  384         // 3 warpgroups (one per gate)
#define MAXB   16384
#define MAXLVL 6

// ---------------- static device scratch -----------------------------------
__device__ float g_H0 [(size_t)MAXB * Hdim];
__device__ float g_HAI[(size_t)MAXLVL * MAXB * Hdim];
__device__ float g_H2 [(size_t)MAXLVL * MAXB * Hdim];
__device__ float g_PR [(size_t)(MAXLVL + 1) * MAXB * Odim];

// packed weights: [gate][k4][j][4] per matrix
#define OFF_WH_A 0
#define OFF_WI_A 49152
#define OFF_WH_F 61440
#define OFF_WI_F 110592
#define OFF_UF   122880
#define OFF_UA   139264
__device__ float g_WP[155648];

typedef unsigned long long u64;
union F4U { float4 f; ulonglong2 u; };

__device__ __forceinline__ void ffma2(u64& d, u64 a, u64 b) {
    asm volatile("fma.rn.f32x2 %0, %1, %2, %0;" : "+l"(d) : "l"(a), "l"(b));
}
__device__ __forceinline__ u64 pack2(float lo, float hi) {
    u64 r; asm("mov.b64 %0, {%1, %2};" : "=l"(r) : "f"(lo), "f"(hi)); return r;
}
__device__ __forceinline__ float f2sum(u64 v) {
    float lo, hi; asm("mov.b64 {%0, %1}, %2;" : "=f"(lo), "=f"(hi) : "l"(v));
    return lo + hi;
}
__device__ __forceinline__ float sigmoidf_(float x) {
    return 1.0f / (1.0f + expf(-x));
}

// ---------------- weight repack prologue ----------------------------------
__device__ __forceinline__ void pack_one(const float* __restrict__ src,
                                         float* __restrict__ dst, int g) {
    int k4 = g >> 7, j = g & 127;
    float4 v;
    v.x = src[(size_t)(4 * k4 + 0) * 128 + j];
    v.y = src[(size_t)(4 * k4 + 1) * 128 + j];
    v.z = src[(size_t)(4 * k4 + 2) * 128 + j];
    v.w = src[(size_t)(4 * k4 + 3) * 128 + j];
    *reinterpret_cast<float4*>(dst + (size_t)g * 4) = v;
}

__global__ void pack_kernel(const float* __restrict__ awh, const float* __restrict__ awi,
                            const float* __restrict__ fwh, const float* __restrict__ fwi,
                            const float* __restrict__ ufw, const float* __restrict__ uaw,
                            float* __restrict__ WP) {
    int g = blockIdx.x * blockDim.x + threadIdx.x;
    if      (g < 12288) pack_one(awh, WP + OFF_WH_A, g);
    else if (g < 15360) pack_one(awi, WP + OFF_WI_A, g - 12288);
    else if (g < 27648) pack_one(fwh, WP + OFF_WH_F, g - 15360);
    else if (g < 30720) pack_one(fwi, WP + OFF_WI_F, g - 27648);
    else if (g < 34816) pack_one(ufw, WP + OFF_UF,   g - 30720);
    else if (g < 38912) pack_one(uaw, WP + OFF_UA,   g - 34816);
}

// ---------------- init: hidden = z @ z2h_w + z2h_b ------------------------
__global__ void __launch_bounds__(NTHR)
init_kernel(const float* __restrict__ z, const float* __restrict__ w,
            const float* __restrict__ b, float* __restrict__ hout) {
    __shared__ float zs[RB][INdim];
    const int j    = threadIdx.x;
    const int row0 = blockIdx.x * RB;

    {
        const float4* src = reinterpret_cast<const float4*>(z + (size_t)row0 * INdim);
        float4* dst = reinterpret_cast<float4*>(&zs[0][0]);
        for (int i = j; i < RB * INdim / 4; i += NTHR) dst[i] = src[i];
    }
    __syncthreads();

    const float bb = b[j];
    float acc[RB];
#pragma unroll
    for (int i = 0; i < RB; i++) acc[i] = bb;
#pragma unroll 4
    for (int k = 0; k < INdim; k += 4) {
        float4 hv[RB];
#pragma unroll
        for (int i = 0; i < RB; i++)
            hv[i] = *reinterpret_cast<const float4*>(&zs[i][k]);
#pragma unroll
        for (int kk = 0; kk < 4; kk++) {
            float wv = w[(size_t)(k + kk) * Hdim + j];
#pragma unroll
            for (int i = 0; i < RB; i++) {
                float h = (kk == 0) ? hv[i].x : (kk == 1) ? hv[i].y
                          : (kk == 2) ? hv[i].z : hv[i].w;
                acc[i] += h * wv;
            }
        }
    }
#pragma unroll
    for (int i = 0; i < RB; i++)
        hout[(size_t)(row0 + i) * Hdim + j] = acc[i];
}

// ---------------- shared accumulation core ---------------------------------
// acc[16] over nk4 k-groups; pact row stride in ulonglong2 units; 8-row halves
// bound register pressure (weights reused across both halves).
__device__ __forceinline__ void accum_k(u64* acc, const float4* __restrict__ pw,
                                        int nk4, const ulonglong2* __restrict__ pact,
                                        int rowStride) {
#pragma unroll 4
    for (int k4 = 0; k4 < nk4; k4++) {
        F4U w; w.f = pw[k4 * 128];
#pragma unroll
        for (int half = 0; half < 2; half++) {
            ulonglong2 a[8];
#pragma unroll
            for (int i = 0; i < 8; i++)
                a[i] = pact[(half * 8 + i) * rowStride + k4];
#pragma unroll
            for (int i = 0; i < 8; i++) {
                ffma2(acc[half * 8 + i], a[i].x, w.u.x);
                ffma2(acc[half * 8 + i], a[i].y, w.u.y);
            }
        }
    }
}

// ---------------- fused node kernel (gate-split warpgroups) ----------------
__global__ void __launch_bounds__(NTHR2, 2)
node_kernel(const float* __restrict__ h_a,
            const float* __restrict__ h2o_w, const float* __restrict__ h2o_b,
            const float* __restrict__ wiP,   const float* __restrict__ bi,
            const float* __restrict__ whP,   const float* __restrict__ bh,
            float* __restrict__ pred_out, float* __restrict__ probs_out,
            float* __restrict__ h_out) {
    __shared__ float hs[RB2 * Hdim];
    __shared__ float ps[RB2 * Odim];
    __shared__ float gR[RB2 * Hdim];
    __shared__ float gZ[RB2 * Hdim];
    __shared__ float xn[RB2 * Hdim];
    const int t    = threadIdx.x;
    const int row0 = blockIdx.x * RB2;

    {
        const float4* src = reinterpret_cast<const float4*>(h_a + (size_t)row0 * Hdim);
        float4* dst = reinterpret_cast<float4*>(hs);
        for (int i = t; i < RB2 * Hdim / 4; i += NTHR2) dst[i] = src[i];
    }
    __syncthreads();

    // ---- pred + softmax: warps 0..7, warp w -> rows 2w, 2w+1; lane = o ----
    {
        const int o = t & 31, w = t >> 5;
        if (w < 8) {
            float acc[2];
            const float bb = h2o_b[o];
            acc[0] = bb; acc[1] = bb;
#pragma unroll 4
            for (int k = 0; k < Hdim; k += 4) {
                float4 h0 = *reinterpret_cast<const float4*>(&hs[(w * 2 + 0) * Hdim + k]);
                float4 h1 = *reinterpret_cast<const float4*>(&hs[(w * 2 + 1) * Hdim + k]);
#pragma unroll
                for (int kk = 0; kk < 4; kk++) {
                    float wv = h2o_w[(size_t)(k + kk) * Odim + o];
                    float a0 = (kk == 0) ? h0.x : (kk == 1) ? h0.y : (kk == 2) ? h0.z : h0.w;
                    float a1 = (kk == 0) ? h1.x : (kk == 1) ? h1.y : (kk == 2) ? h1.z : h1.w;
                    acc[0] += a0 * wv;
                    acc[1] += a1 * wv;
                }
            }
#pragma unroll
            for (int i = 0; i < 2; i++) {
                int r = w * 2 + i;
                float v = acc[i];
                pred_out[(size_t)(row0 + r) * Odim + o] = v;
                float m = v;
#pragma unroll
                for (int s = 16; s > 0; s >>= 1)
                    m = fmaxf(m, __shfl_xor_sync(0xffffffffu, m, s));
                float e = expf(v - m);
                float ssum = e;
#pragma unroll
                for (int s = 16; s > 0; s >>= 1)
                    ssum += __shfl_xor_sync(0xffffffffu, ssum, s);
                float p = e / ssum;
                ps[r * Odim + o] = p;
                probs_out[(size_t)(row0 + r) * Odim + o] = p;
            }
        }
    }
    __syncthreads();

    // ---- gate accumulation: warpgroup g owns gate g ----
    const int j = t & 127, g = t >> 7;
    const float4* pw  = reinterpret_cast<const float4*>(whP) + g * 4096 + j;
    const float4* pwi = reinterpret_cast<const float4*>(wiP) + g * 1024 + j;
    const ulonglong2* ph = reinterpret_cast<const ulonglong2*>(hs);  // stride 32
    const ulonglong2* pp = reinterpret_cast<const ulonglong2*>(ps);  // stride 8

    u64 acc[RB2];
    if (g < 2) {
        const float b0 = bi[g * Hdim + j] + bh[g * Hdim + j];
#pragma unroll
        for (int i = 0; i < RB2; i++) acc[i] = pack2(b0, 0.0f);
        accum_k(acc, pwi, Odim / 4, pp, 8);
        accum_k(acc, pw,  Hdim / 4, ph, 32);
        float* dstg = (g == 0) ? gR : gZ;
#pragma unroll
        for (int i = 0; i < RB2; i++)
            dstg[i * Hdim + j] = sigmoidf_(f2sum(acc[i]));
    } else {
        const float bx = bi[2 * Hdim + j];
#pragma unroll
        for (int i = 0; i < RB2; i++) acc[i] = pack2(bx, 0.0f);
        accum_k(acc, pwi, Odim / 4, pp, 8);
#pragma unroll
        for (int i = 0; i < RB2; i++)
            xn[i * Hdim + j] = f2sum(acc[i]);
        const float bh2 = bh[2 * Hdim + j];
#pragma unroll
        for (int i = 0; i < RB2; i++) acc[i] = pack2(bh2, 0.0f);
        accum_k(acc, pw, Hdim / 4, ph, 32);
    }
    __syncthreads();

    if (g == 2) {
        float* po = h_out + (size_t)row0 * Hdim + j;
#pragma unroll
        for (int i = 0; i < RB2; i++) {
            float rg = gR[i * Hdim + j];
            float zg = gZ[i * Hdim + j];
            float n  = tanhf(xn[i * Hdim + j] + rg * f2sum(acc[i]));
            float hv = hs[i * Hdim + j];
            po[i * Hdim] = (1.0f - zg) * n + zg * hv;
        }
    }
}

// ---------------- fused combine kernel (gate-split + merge) ----------------
__global__ void __launch_bounds__(NTHR2, 2)
combine_kernel(const float* __restrict__ probs_fc,
               const float* __restrict__ h_ai, const float* __restrict__ h_a,
               const float* __restrict__ wiP,  const float* __restrict__ bi,
               const float* __restrict__ whP,  const float* __restrict__ bh,
               const float* __restrict__ ufP,  const float* __restrict__ ufb,
               const float* __restrict__ uaP,  const float* __restrict__ uab,
               float* __restrict__ h2_out) {
    __shared__ float hs[RB2 * Hdim];   // h_ai, later h_a
    __shared__ float ps[RB2 * Odim];
    __shared__ float gR[RB2 * Hdim];
    __shared__ float gZ[RB2 * Hdim];
    __shared__ float xn[RB2 * Hdim];
    __shared__ float hf[RB2 * Hdim];
    const int t    = threadIdx.x;
    const int row0 = blockIdx.x * RB2;

    {
        const float4* src = reinterpret_cast<const float4*>(h_ai + (size_t)row0 * Hdim);
        float4* dst = reinterpret_cast<float4*>(hs);
        for (int i = t; i < RB2 * Hdim / 4; i += NTHR2) dst[i] = src[i];
        const float4* psrc = reinterpret_cast<const float4*>(probs_fc + (size_t)row0 * Odim);
        float4* pdst = reinterpret_cast<float4*>(ps);
        if (t < RB2 * Odim / 4) pdst[t] = psrc[t];
    }
    __syncthreads();

    const int j = t & 127, g = t >> 7;
    const float4* pw  = reinterpret_cast<const float4*>(whP) + g * 4096 + j;
    const float4* pwi = reinterpret_cast<const float4*>(wiP) + g * 1024 + j;
    const ulonglong2* ph = reinterpret_cast<const ulonglong2*>(hs);
    const ulonglong2* pp = reinterpret_cast<const ulonglong2*>(ps);

    u64 acc[RB2];
    if (g < 2) {
        const float b0 = bi[g * Hdim + j] + bh[g * Hdim + j];
#pragma unroll
        for (int i = 0; i < RB2; i++) acc[i] = pack2(b0, 0.0f);
        accum_k(acc, pwi, Odim / 4, pp, 8);
        accum_k(acc, pw,  Hdim / 4, ph, 32);
        float* dstg = (g == 0) ? gR : gZ;
#pragma unroll
        for (int i = 0; i < RB2; i++)
            dstg[i * Hdim + j] = sigmoidf_(f2sum(acc[i]));
    } else {
        const float bx = bi[2 * Hdim + j];
#pragma unroll
        for (int i = 0; i < RB2; i++) acc[i] = pack2(bx, 0.0f);
        accum_k(acc, pwi, Odim / 4, pp, 8);
#pragma unroll
        for (int i = 0; i < RB2; i++)
            xn[i * Hdim + j] = f2sum(acc[i]);
        const float bh2 = bh[2 * Hdim + j];
#pragma unroll
        for (int i = 0; i < RB2; i++) acc[i] = pack2(bh2, 0.0f);
        accum_k(acc, pw, Hdim / 4, ph, 32);
    }
    __syncthreads();

    if (g == 2) {
#pragma unroll
        for (int i = 0; i < RB2; i++) {
            float rg = gR[i * Hdim + j];
            float zg = gZ[i * Hdim + j];
            float n  = tanhf(xn[i * Hdim + j] + rg * f2sum(acc[i]));
            float hv = hs[i * Hdim + j];
            hf[i * Hdim + j] = (1.0f - zg) * n + zg * hv;
        }
    }
    __syncthreads();
    // reload hs with h_a
    {
        const float4* src = reinterpret_cast<const float4*>(h_a + (size_t)row0 * Hdim);
        float4* dst = reinterpret_cast<float4*>(hs);
        for (int i = t; i < RB2 * Hdim / 4; i += NTHR2) dst[i] = src[i];
    }
    __syncthreads();

    // merge: h2 = tanh(hf@ufw + hs@uaw + ufb + uab); warpgroup g -> row slice
    {
        const int r0 = g * 6;
        const int nr = (g < 2) ? 6 : 4;              // rows 0-5 / 6-11 / 12-15
        const float bb = ufb[j] + uab[j];
        u64 macc[6];
#pragma unroll
        for (int i = 0; i < 6; i++) macc[i] = pack2(bb, 0.0f);

        const float4* pf = reinterpret_cast<const float4*>(ufP) + j;
        const float4* pa = reinterpret_cast<const float4*>(uaP) + j;
        const ulonglong2* phf = reinterpret_cast<const ulonglong2*>(hf);
        const ulonglong2* phs = reinterpret_cast<const ulonglong2*>(hs);
#pragma unroll 4
        for (int k4 = 0; k4 < Hdim / 4; k4++) {
            F4U wf, wa;
            wf.f = pf[k4 * 128];
            wa.f = pa[k4 * 128];
#pragma unroll
            for (int i = 0; i < 6; i++) {
                if (i < nr) {
                    ulonglong2 hv = phf[(r0 + i) * 32 + k4];
                    ulonglong2 av = phs[(r0 + i) * 32 + k4];
                    ffma2(macc[i], hv.x, wf.u.x); ffma2(macc[i], hv.y, wf.u.y);
                    ffma2(macc[i], av.x, wa.u.x); ffma2(macc[i], av.y, wa.u.y);
                }
            }
        }
        float* po = h2_out + (size_t)(row0 + r0) * Hdim + j;
#pragma unroll
        for (int i = 0; i < 6; i++)
            if (i < nr) po[i * Hdim] = tanhf(f2sum(macc[i]));
    }
}

// ---------------- host-side tree orchestration (single stream) ------------
struct EmitCtx {
    const float *h2o_w, *h2o_b;
    const float *abi, *abh, *fbi, *fbh;
    const float *uab, *ufb;
    const float *awiP, *awhP, *fwiP, *fwhP, *ufP, *uaP;
    float* out;
    float *HAI, *H2, *PR;
    int B, grid, idx;
};

static void emit_node(EmitCtx& P, int lvl, int d, const float* h_in) {
    float* probs = P.PR  + (size_t)lvl * P.B * Odim;
    float* h_ai  = P.HAI + (size_t)lvl * P.B * Hdim;
    node_kernel<<<P.grid, NTHR2>>>(h_in, P.h2o_w, P.h2o_b,
                                   P.awiP, P.abi, P.awhP, P.abh,
                                   P.out + (size_t)P.idx * P.B * Odim,
                                   probs, h_ai);
    P.idx++;
    if (d > 0) {
        emit_node(P, lvl + 1, d - 1, h_ai);
        float* h2 = P.H2 + (size_t)lvl * P.B * Hdim;
        combine_kernel<<<P.grid, NTHR2>>>(P.PR + (size_t)(lvl + 1) * P.B * Odim,
                                          h_ai, h_in,
                                          P.fwiP, P.fbi, P.fwhP, P.fbh,
                                          P.ufP, P.ufb, P.uaP, P.uab, h2);
        emit_node(P, lvl + 1, d - 1, h2);
    }
}

extern "C" void kernel_launch(void* const* d_in, const int* in_sizes, int n_in,
                              void* d_out, int out_size) {
    const float* z      = (const float*)d_in[0];
    const float* z2h_w  = (const float*)d_in[1];
    const float* z2h_b  = (const float*)d_in[2];
    const float* h2o_w  = (const float*)d_in[3];
    const float* h2o_b  = (const float*)d_in[4];
    const float* awi    = (const float*)d_in[5];
    const float* abi    = (const float*)d_in[6];
    const float* awh    = (const float*)d_in[7];
    const float* abh    = (const float*)d_in[8];
    const float* fwi    = (const float*)d_in[9];
    const float* fbi    = (const float*)d_in[10];
    const float* fwh    = (const float*)d_in[11];
    const float* fbh    = (const float*)d_in[12];
    const float* uaw    = (const float*)d_in[13];
    const float* uab    = (const float*)d_in[14];
    const float* ufw    = (const float*)d_in[15];
    const float* ufb    = (const float*)d_in[16];

    const int H  = in_sizes[2];               // 128
    const int O  = in_sizes[4];               // 32
    const int IN = in_sizes[1] / H;           // 64
    const int B  = in_sizes[0] / IN;          // 16384
    const int nn = out_size / (B * O);        // tree nodes (31)
    int depth = 0;
    while (((2 << depth) - 1) < nn) depth++;

    float *H0p, *HAIp, *H2p, *PRp, *WPp;
    cudaGetSymbolAddress((void**)&H0p,  g_H0);
    cudaGetSymbolAddress((void**)&HAIp, g_HAI);
    cudaGetSymbolAddress((void**)&H2p,  g_H2);
    cudaGetSymbolAddress((void**)&PRp,  g_PR);
    cudaGetSymbolAddress((void**)&WPp,  g_WP);

    pack_kernel<<<(38912 + 255) / 256, 256>>>(awh, awi, fwh, fwi, ufw, uaw, WPp);
    init_kernel<<<B / RB, NTHR>>>(z, z2h_w, z2h_b, H0p);

    EmitCtx P;
    P.h2o_w = h2o_w; P.h2o_b = h2o_b;
    P.abi = abi; P.abh = abh; P.fbi = fbi; P.fbh = fbh;
    P.uab = uab; P.ufb = ufb;
    P.awiP = WPp + OFF_WI_A; P.awhP = WPp + OFF_WH_A;
    P.fwiP = WPp + OFF_WI_F; P.fwhP = WPp + OFF_WH_F;
    P.ufP  = WPp + OFF_UF;   P.uaP  = WPp + OFF_UA;
    P.out  = (float*)d_out;
    P.HAI = HAIp; P.H2 = H2p; P.PR = PRp;
    P.B = B; P.grid = B / RB2; P.idx = 0;

    emit_node(P, 0, depth, H0p);
}

// round 10
// speedup vs baseline: 1.1973x; 1.1971x over previous
#include <cuda_runtime.h>
#include <cuda_bf16.h>
#include <cstdint>

#define Hdim 128
#define Odim 32
#define INdim 64
#define RB 8
#define NTHR 128
#define MAXB 16384
#define MAXLVL 6

__device__ float g_H0 [(size_t)MAXB * Hdim];
__device__ float g_HAI[(size_t)MAXLVL * MAXB * Hdim];
__device__ float g_H2 [(size_t)MAXLVL * MAXB * Hdim];
__device__ float g_PR [(size_t)(MAXLVL + 1) * MAXB * Odim];

#define OFF_WH_F 0
#define OFF_WI_F 49152
#define OFF_UF   61440
#define OFF_UA   77824
__device__ float g_WP[94208];
__device__ float g_WPRED[4096];
__device__ __align__(1024) unsigned char g_WTC[327680]; // [2 plane][5 chunk][512 n][64B]

typedef unsigned long long u64;
union F4U { float4 f; ulonglong2 u; };

__device__ __forceinline__ void ffma2(u64& d, u64 a, u64 b) {
    asm volatile("fma.rn.f32x2 %0, %1, %2, %0;" : "+l"(d) : "l"(a), "l"(b));
}
__device__ __forceinline__ u64 pack2(float lo, float hi) {
    u64 r; asm("mov.b64 %0, {%1, %2};" : "=l"(r) : "f"(lo), "f"(hi)); return r;
}
__device__ __forceinline__ float f2sum(u64 v) {
    float lo, hi; asm("mov.b64 {%0, %1}, %2;" : "=f"(lo), "=f"(hi) : "l"(v));
    return lo + hi;
}
__device__ __forceinline__ float sigmoidf_(float x) { return 1.0f / (1.0f + expf(-x)); }
__device__ __forceinline__ uint32_t smem_u32(const void* p) {
    uint32_t a;
    asm("{ .reg .u64 t; cvta.to.shared.u64 t, %1; cvt.u32.u64 %0, t; }" : "=r"(a) : "l"(p));
    return a;
}
__device__ __forceinline__ void ldsm4(uint32_t* r, uint32_t a) {
    asm volatile("ldmatrix.sync.aligned.m8n8.x4.shared.b16 {%0,%1,%2,%3}, [%4];"
        : "=r"(r[0]),"=r"(r[1]),"=r"(r[2]),"=r"(r[3]) : "r"(a));
}
__device__ __forceinline__ void ldsm2(uint32_t* r, uint32_t a) {
    asm volatile("ldmatrix.sync.aligned.m8n8.x2.shared.b16 {%0,%1}, [%2];"
        : "=r"(r[0]),"=r"(r[1]) : "r"(a));
}
__device__ __forceinline__ void mma16816(float* c, const uint32_t* a, const uint32_t* b) {
    asm volatile("mma.sync.aligned.m16n8k16.row.col.f32.bf16.bf16.f32 "
        "{%0,%1,%2,%3}, {%4,%5,%6,%7}, {%8,%9}, {%0,%1,%2,%3};"
        : "+f"(c[0]),"+f"(c[1]),"+f"(c[2]),"+f"(c[3])
        : "r"(a[0]),"r"(a[1]),"r"(a[2]),"r"(a[3]),"r"(b[0]),"r"(b[1]));
}
#define CPA16(d, s) asm volatile("cp.async.cg.shared.global [%0], [%1], 16;" :: "r"(d), "l"(s))
#define CPCOMMIT()  asm volatile("cp.async.commit_group;")
#define CPWAIT1()   asm volatile("cp.async.wait_group 1;")
#define CPWAIT0()   asm volatile("cp.async.wait_group 0;")

// -------- prologue packs --------
__device__ __forceinline__ void pack_one(const float* __restrict__ s, float* __restrict__ d, int g) {
    int k4 = g >> 7, j = g & 127;
    float4 v;
    v.x = s[(size_t)(4*k4+0)*128+j]; v.y = s[(size_t)(4*k4+1)*128+j];
    v.z = s[(size_t)(4*k4+2)*128+j]; v.w = s[(size_t)(4*k4+3)*128+j];
    *reinterpret_cast<float4*>(d + (size_t)g*4) = v;
}
__global__ void pack_kernel(const float* __restrict__ fwh, const float* __restrict__ fwi,
                            const float* __restrict__ ufw, const float* __restrict__ uaw,
                            const float* __restrict__ h2o_w,
                            float* __restrict__ WP, float* __restrict__ WPRED) {
    int g = blockIdx.x * blockDim.x + threadIdx.x;
    if      (g < 12288) pack_one(fwh, WP + OFF_WH_F, g);
    else if (g < 15360) pack_one(fwi, WP + OFF_WI_F, g - 12288);
    else if (g < 19456) pack_one(ufw, WP + OFF_UF,   g - 15360);
    else if (g < 23552) pack_one(uaw, WP + OFF_UA,   g - 19456);
    else if (g < 25600) {
        int g2 = g - 23552, k2 = g2 >> 5, o = g2 & 31;
        WPRED[g2*2]   = h2o_w[(size_t)(2*k2)*32+o];
        WPRED[g2*2+1] = h2o_w[(size_t)(2*k2+1)*32+o];
    }
}
__global__ void pack_wtc(const float* __restrict__ awh, const float* __restrict__ awi,
                         unsigned char* __restrict__ WTC) {
    int id = blockIdx.x * blockDim.x + threadIdx.x;
    if (id >= 2560) return;
    int c = id / 512, n = id % 512;
    int gate = n >> 7, j = n & 127;
    for (int kk = 0; kk < 32; kk++) {
        int gk = c*32 + kk;
        float w;
        if      (gate == 0) w = gk < 128 ? awh[(size_t)gk*128 + j] : awi[(size_t)(gk-128)*128 + j];
        else if (gate == 1) w = gk < 128 ? awh[16384 + (size_t)gk*128 + j] : awi[4096 + (size_t)(gk-128)*128 + j];
        else if (gate == 2) w = gk < 128 ? awh[32768 + (size_t)gk*128 + j] : 0.0f;
        else                w = gk < 128 ? 0.0f : awi[8192 + (size_t)(gk-128)*128 + j];
        __nv_bfloat16 hi = __float2bfloat16(w);
        __nv_bfloat16 lo = __float2bfloat16(w - __bfloat162float(hi));
        size_t off = (size_t)c*32768 + (size_t)n*64 + kk*2;
        *(__nv_bfloat16*)(WTC + off)          = hi;
        *(__nv_bfloat16*)(WTC + 163840 + off) = lo;
    }
}

__global__ void __launch_bounds__(NTHR)
init_kernel(const float* __restrict__ z, const float* __restrict__ w,
            const float* __restrict__ b, float* __restrict__ hout) {
    __shared__ float zs[RB][INdim];
    const int j = threadIdx.x, row0 = blockIdx.x * RB;
    {
        const float4* src = reinterpret_cast<const float4*>(z + (size_t)row0 * INdim);
        float4* dst = reinterpret_cast<float4*>(&zs[0][0]);
        for (int i = j; i < RB * INdim / 4; i += NTHR) dst[i] = src[i];
    }
    __syncthreads();
    const float bb = b[j];
    float acc[RB];
#pragma unroll
    for (int i = 0; i < RB; i++) acc[i] = bb;
#pragma unroll 4
    for (int k = 0; k < INdim; k += 4) {
        float4 hv[RB];
#pragma unroll
        for (int i = 0; i < RB; i++) hv[i] = *reinterpret_cast<const float4*>(&zs[i][k]);
#pragma unroll
        for (int kk = 0; kk < 4; kk++) {
            float wv = w[(size_t)(k+kk)*Hdim + j];
#pragma unroll
            for (int i = 0; i < RB; i++) {
                float h = (kk==0)?hv[i].x:(kk==1)?hv[i].y:(kk==2)?hv[i].z:hv[i].w;
                acc[i] += h * wv;
            }
        }
    }
#pragma unroll
    for (int i = 0; i < RB; i++) hout[(size_t)(row0+i)*Hdim + j] = acc[i];
}

// ======== mma.sync node kernel ========
#define SM_AHI  0
#define SM_ALO  21504
#define SM_B    43008
#define SMEM_TC 206848
#define APITCH  336

__device__ __forceinline__ void node_copy(uint32_t sb, const unsigned char* WTC, int c, int t) {
    uint32_t dst = sb + SM_B + (uint32_t)(c & 1) * 81920u + (uint32_t)t * 80u;
    const unsigned char* s0 = WTC + (size_t)c*32768 + (size_t)t*64;
#pragma unroll
    for (int q = 0; q < 4; q++) CPA16(dst + q*16, s0 + q*16);
    dst += 40960u;
    s0 += 163840;
#pragma unroll
    for (int q = 0; q < 4; q++) CPA16(dst + q*16, s0 + q*16);
}

__global__ void __launch_bounds__(512, 1)
node_tc(const float* __restrict__ h_a,
        const float* __restrict__ wpred, const float* __restrict__ h2o_b,
        const unsigned char* __restrict__ WTC,
        const float* __restrict__ abi, const float* __restrict__ abh,
        float* __restrict__ pred_out, float* __restrict__ probs_out,
        float* __restrict__ h_out) {
    extern __shared__ __align__(128) unsigned char smem[];
    const uint32_t sb = smem_u32(smem);
    const int t = threadIdx.x, wid = t >> 5, lane = t & 31;
    const int row0 = blockIdx.x * 64;

    for (int i = t; i < 2048; i += 512) {   // h -> A hi/lo (cols 0-127)
        int row = i >> 5, k4 = i & 31;
        float4 v = ((const float4*)(h_a + (size_t)(row0+row)*Hdim))[k4];
        __nv_bfloat162 h01 = __floats2bfloat162_rn(v.x, v.y);
        __nv_bfloat162 h23 = __floats2bfloat162_rn(v.z, v.w);
        __nv_bfloat162 l01 = __floats2bfloat162_rn(v.x-__bfloat162float(h01.x), v.y-__bfloat162float(h01.y));
        __nv_bfloat162 l23 = __floats2bfloat162_rn(v.z-__bfloat162float(h23.x), v.w-__bfloat162float(h23.y));
        uint32_t o = (uint32_t)row*APITCH + k4*8;
        *(__nv_bfloat162*)(smem + SM_AHI + o)     = h01;
        *(__nv_bfloat162*)(smem + SM_AHI + o + 4) = h23;
        *(__nv_bfloat162*)(smem + SM_ALO + o)     = l01;
        *(__nv_bfloat162*)(smem + SM_ALO + o + 4) = l23;
    }
    node_copy(sb, WTC, 0, t);
    CPCOMMIT();

    {   // pred fp32 + softmax; probs -> A cols 128-159
        const float bo = h2o_b[lane];
        const u64* WPp = (const u64*)wpred;
        for (int rr = 0; rr < 4; rr++) {
            int row = wid*4 + rr, grow = row0 + row;
            const u64* hr = (const u64*)(h_a + (size_t)grow*Hdim);
            u64 acc = pack2(bo, 0.0f);
#pragma unroll 8
            for (int k2 = 0; k2 < 64; k2++) ffma2(acc, hr[k2], WPp[k2*32 + lane]);
            float v = f2sum(acc), m = v;
#pragma unroll
            for (int s = 16; s > 0; s >>= 1) m = fmaxf(m, __shfl_xor_sync(~0u, m, s));
            float e = expf(v - m), ss = e;
#pragma unroll
            for (int s = 16; s > 0; s >>= 1) ss += __shfl_xor_sync(~0u, ss, s);
            float p = e / ss;
            pred_out[(size_t)grow*Odim + lane]  = v;
            probs_out[(size_t)grow*Odim + lane] = p;
            __nv_bfloat16 ph = __float2bfloat16(p);
            __nv_bfloat16 pl = __float2bfloat16(p - __bfloat162float(ph));
            uint32_t o = (uint32_t)row*APITCH + 256 + 2*lane;
            *(__nv_bfloat16*)(smem + SM_AHI + o) = ph;
            *(__nv_bfloat16*)(smem + SM_ALO + o) = pl;
        }
    }

    const int wm = wid & 3, wn = wid >> 2, l2 = lane & 15;
    float acc[16][4];
#pragma unroll
    for (int i = 0; i < 16; i++)
#pragma unroll
        for (int q = 0; q < 4; q++) acc[i][q] = 0.0f;

    const uint32_t abase = sb + SM_AHI + (uint32_t)(wm*16 + (lane & 15))*APITCH + (uint32_t)(lane >> 4)*16;
    const uint32_t bln   = (uint32_t)(l2 & 7)*80u + (uint32_t)(l2 >> 3)*16u;

    for (int c = 0; c < 5; c++) {
        if (c < 4) { node_copy(sb, WTC, c+1, t); CPCOMMIT(); CPWAIT1(); }
        else CPWAIT0();
        __syncthreads();
        uint32_t bbuf = sb + SM_B + (uint32_t)(c & 1)*81920u;
#pragma unroll
        for (int kk = 0; kk < 2; kk++) {
            uint32_t ah[4], al[4];
            ldsm4(ah, abase + (uint32_t)(c*32 + kk*16)*2);
            ldsm4(al, abase + 21504u + (uint32_t)(c*32 + kk*16)*2);
#pragma unroll
            for (int t16 = 0; t16 < 16; t16++) {
                uint32_t ba = bbuf + (uint32_t)(wn*128 + t16*8)*80u + bln + (uint32_t)kk*32;
                uint32_t bh[2], bl[2];
                ldsm2(bh, ba);
                ldsm2(bl, ba + 40960u);
                mma16816(acc[t16], ah, bh);
                mma16816(acc[t16], al, bh);
                mma16816(acc[t16], ah, bl);
            }
        }
        __syncthreads();
    }

    {   // exchange gates via smem (overlay B area)
        float* exch = (float*)(smem + SM_B);
        int r1 = wm*16 + (lane >> 2), base = wn*8448;
#pragma unroll
        for (int t16 = 0; t16 < 16; t16++) {
            int j0 = t16*8 + 2*(lane & 3);
            *(float2*)&exch[base + r1*132 + j0]       = make_float2(acc[t16][0], acc[t16][1]);
            *(float2*)&exch[base + (r1+8)*132 + j0]   = make_float2(acc[t16][2], acc[t16][3]);
        }
    }
    __syncthreads();
    {   // GRU epilogue: thread -> row t>>3, cols (t&7)*16..+15
        const float* exch = (const float*)(smem + SM_B);
        int row = t >> 3, j0 = (t & 7)*16;
#pragma unroll
        for (int b = 0; b < 4; b++) {
            int j = j0 + b*4;
            float4 vr = *(const float4*)&exch[0*8448 + row*132 + j];
            float4 vz = *(const float4*)&exch[1*8448 + row*132 + j];
            float4 vh = *(const float4*)&exch[2*8448 + row*132 + j];
            float4 vx = *(const float4*)&exch[3*8448 + row*132 + j];
            float4 bir = *(const float4*)&abi[j],      bhr = *(const float4*)&abh[j];
            float4 biz = *(const float4*)&abi[128+j],  bhz = *(const float4*)&abh[128+j];
            float4 bin = *(const float4*)&abi[256+j],  bhn = *(const float4*)&abh[256+j];
            float4 hv = *(const float4*)(h_a + (size_t)(row0+row)*Hdim + j);
            float4 out;
            {
                float rg = sigmoidf_(vr.x + bir.x + bhr.x);
                float zg = sigmoidf_(vz.x + biz.x + bhz.x);
                float nn = tanhf(vx.x + bin.x + rg*(vh.x + bhn.x));
                out.x = (1.0f - zg)*nn + zg*hv.x;
                rg = sigmoidf_(vr.y + bir.y + bhr.y);
                zg = sigmoidf_(vz.y + biz.y + bhz.y);
                nn = tanhf(vx.y + bin.y + rg*(vh.y + bhn.y));
                out.y = (1.0f - zg)*nn + zg*hv.y;
                rg = sigmoidf_(vr.z + bir.z + bhr.z);
                zg = sigmoidf_(vz.z + biz.z + bhz.z);
                nn = tanhf(vx.z + bin.z + rg*(vh.z + bhn.z));
                out.z = (1.0f - zg)*nn + zg*hv.z;
                rg = sigmoidf_(vr.w + bir.w + bhr.w);
                zg = sigmoidf_(vz.w + biz.w + bhz.w);
                nn = tanhf(vx.w + bin.w + rg*(vh.w + bhn.w));
                out.w = (1.0f - zg)*nn + zg*hv.w;
            }
            *(float4*)(h_out + (size_t)(row0+row)*Hdim + j) = out;
        }
    }
}

// ======== combine kernel (R5 FFMA2, proven) ========
__device__ __forceinline__ void gru_rows8(
    const float* __restrict__ hsf, const float* __restrict__ psf, int j,
    const float* __restrict__ whP, const float* __restrict__ wiP,
    const float* __restrict__ bi,  const float* __restrict__ bh, float out[RB]) {
    const float br_ = bi[j] + bh[j];
    const float bz_ = bi[128+j] + bh[128+j];
    const float bxn = bi[256+j];
    const float bhn = bh[256+j];
    u64 ar[RB], az[RB], anh[RB], anx[RB];
#pragma unroll
    for (int i = 0; i < RB; i++) {
        ar[i]=pack2(br_,0.f); az[i]=pack2(bz_,0.f); anh[i]=pack2(bhn,0.f); anx[i]=pack2(bxn,0.f);
    }
    const float4* pw = reinterpret_cast<const float4*>(whP) + j;
    const ulonglong2* ph = reinterpret_cast<const ulonglong2*>(hsf);
#pragma unroll 4
    for (int k4 = 0; k4 < Hdim/4; k4++) {
        F4U w0, w1, w2;
        w0.f = pw[k4*128]; w1.f = pw[k4*128+4096]; w2.f = pw[k4*128+8192];
        ulonglong2 h[RB];
#pragma unroll
        for (int i = 0; i < RB; i++) h[i] = ph[i*32 + k4];
#pragma unroll
        for (int i = 0; i < RB; i++) {
            ffma2(ar[i],h[i].x,w0.u.x); ffma2(az[i],h[i].x,w1.u.x); ffma2(anh[i],h[i].x,w2.u.x);
            ffma2(ar[i],h[i].y,w0.u.y); ffma2(az[i],h[i].y,w1.u.y); ffma2(anh[i],h[i].y,w2.u.y);
        }
    }
    const float4* pwi = reinterpret_cast<const float4*>(wiP) + j;
    const ulonglong2* pp = reinterpret_cast<const ulonglong2*>(psf);
#pragma unroll
    for (int k4 = 0; k4 < Odim/4; k4++) {
        F4U w0, w1, w2;
        w0.f = pwi[k4*128]; w1.f = pwi[k4*128+1024]; w2.f = pwi[k4*128+2048];
        ulonglong2 p[RB];
#pragma unroll
        for (int i = 0; i < RB; i++) p[i] = pp[i*8 + k4];
#pragma unroll
        for (int i = 0; i < RB; i++) {
            ffma2(ar[i],p[i].x,w0.u.x); ffma2(az[i],p[i].x,w1.u.x); ffma2(anx[i],p[i].x,w2.u.x);
            ffma2(ar[i],p[i].y,w0.u.y); ffma2(az[i],p[i].y,w1.u.y); ffma2(anx[i],p[i].y,w2.u.y);
        }
    }
#pragma unroll
    for (int i = 0; i < RB; i++) {
        float rg = sigmoidf_(f2sum(ar[i]));
        float zg = sigmoidf_(f2sum(az[i]));
        float n  = tanhf(f2sum(anx[i]) + rg*f2sum(anh[i]));
        out[i] = (1.0f - zg)*n + zg*hsf[i*Hdim + j];
    }
}

__global__ void __launch_bounds__(NTHR, 4)
combine_kernel(const float* __restrict__ probs_fc,
               const float* __restrict__ h_ai, const float* __restrict__ h_a,
               const float* __restrict__ wiP,  const float* __restrict__ bi,
               const float* __restrict__ whP,  const float* __restrict__ bh,
               const float* __restrict__ ufP,  const float* __restrict__ ufb,
               const float* __restrict__ uaP,  const float* __restrict__ uab,
               float* __restrict__ h2_out) {
    __shared__ float hs[RB * Hdim];
    __shared__ float ps[RB * Odim];
    __shared__ float hf[RB * Hdim];
    const int t = threadIdx.x, row0 = blockIdx.x * RB;
    {
        const float4* src = reinterpret_cast<const float4*>(h_ai + (size_t)row0*Hdim);
        float4* dst = reinterpret_cast<float4*>(hs);
#pragma unroll
        for (int i = t; i < RB*Hdim/4; i += NTHR) dst[i] = src[i];
        const float4* psrc = reinterpret_cast<const float4*>(probs_fc + (size_t)row0*Odim);
        if (t < RB*Odim/4) reinterpret_cast<float4*>(ps)[t] = psrc[t];
    }
    __syncthreads();
    float out[RB];
    gru_rows8(hs, ps, t, whP, wiP, bi, bh, out);
#pragma unroll
    for (int i = 0; i < RB; i++) hf[i*Hdim + t] = out[i];
    __syncthreads();
    {
        const float4* src = reinterpret_cast<const float4*>(h_a + (size_t)row0*Hdim);
        float4* dst = reinterpret_cast<float4*>(hs);
#pragma unroll
        for (int i = t; i < RB*Hdim/4; i += NTHR) dst[i] = src[i];
    }
    __syncthreads();
    const float bb = ufb[t] + uab[t];
    u64 acc[RB];
#pragma unroll
    for (int i = 0; i < RB; i++) acc[i] = pack2(bb, 0.0f);
    const float4* pf = reinterpret_cast<const float4*>(ufP) + t;
    const float4* pa = reinterpret_cast<const float4*>(uaP) + t;
    const ulonglong2* phf = reinterpret_cast<const ulonglong2*>(hf);
    const ulonglong2* phs = reinterpret_cast<const ulonglong2*>(hs);
#pragma unroll 4
    for (int k4 = 0; k4 < Hdim/4; k4++) {
        F4U wf, wa;
        wf.f = pf[k4*128]; wa.f = pa[k4*128];
        ulonglong2 hv[RB], av[RB];
#pragma unroll
        for (int i = 0; i < RB; i++) { hv[i]=phf[i*32+k4]; av[i]=phs[i*32+k4]; }
#pragma unroll
        for (int i = 0; i < RB; i++) {
            ffma2(acc[i],hv[i].x,wf.u.x); ffma2(acc[i],hv[i].y,wf.u.y);
            ffma2(acc[i],av[i].x,wa.u.x); ffma2(acc[i],av[i].y,wa.u.y);
        }
    }
    float* po = h2_out + (size_t)row0*Hdim + t;
#pragma unroll
    for (int i = 0; i < RB; i++) po[i*Hdim] = tanhf(f2sum(acc[i]));
}

// ======== host orchestration ========
struct EmitCtx {
    const float *wpred, *h2o_b, *abi, *abh, *fbi, *fbh, *uab, *ufb;
    const float *fwiP, *fwhP, *ufP, *uaP;
    const unsigned char *WTC;
    float *out, *HAI, *H2, *PR;
    int B, idx;
};

static void emit_node(EmitCtx& P, int lvl, int d, const float* h_in) {
    float* probs = P.PR  + (size_t)lvl * P.B * Odim;
    float* h_ai  = P.HAI + (size_t)lvl * P.B * Hdim;
    node_tc<<<P.B / 64, 512, SMEM_TC>>>(h_in, P.wpred, P.h2o_b, P.WTC, P.abi, P.abh,
                                        P.out + (size_t)P.idx * P.B * Odim, probs, h_ai);
    P.idx++;
    if (d > 0) {
        emit_node(P, lvl + 1, d - 1, h_ai);
        float* h2 = P.H2 + (size_t)lvl * P.B * Hdim;
        combine_kernel<<<P.B / RB, NTHR>>>(P.PR + (size_t)(lvl+1) * P.B * Odim,
                                           h_ai, h_in, P.fwiP, P.fbi, P.fwhP, P.fbh,
                                           P.ufP, P.ufb, P.uaP, P.uab, h2);
        emit_node(P, lvl + 1, d - 1, h2);
    }
}

extern "C" void kernel_launch(void* const* d_in, const int* in_sizes, int n_in,
                              void* d_out, int out_size) {
    const float* z     = (const float*)d_in[0];
    const float* z2h_w = (const float*)d_in[1];
    const float* z2h_b = (const float*)d_in[2];
    const float* h2o_w = (const float*)d_in[3];
    const float* h2o_b = (const float*)d_in[4];
    const float* awi   = (const float*)d_in[5];
    const float* abi   = (const float*)d_in[6];
    const float* awh   = (const float*)d_in[7];
    const float* abh   = (const float*)d_in[8];
    const float* fwi   = (const float*)d_in[9];
    const float* fbi   = (const float*)d_in[10];
    const float* fwh   = (const float*)d_in[11];
    const float* fbh   = (const float*)d_in[12];
    const float* uaw   = (const float*)d_in[13];
    const float* uab   = (const float*)d_in[14];
    const float* ufw   = (const float*)d_in[15];
    const float* ufb   = (const float*)d_in[16];

    const int H  = in_sizes[2];
    const int O  = in_sizes[4];
    const int IN = in_sizes[1] / H;
    const int B  = in_sizes[0] / IN;
    const int nn = out_size / (B * O);
    int depth = 0;
    while (((2 << depth) - 1) < nn) depth++;

    float *H0p, *HAIp, *H2p, *PRp, *WPp, *WPRp;
    unsigned char *WTCp;
    cudaGetSymbolAddress((void**)&H0p,  g_H0);
    cudaGetSymbolAddress((void**)&HAIp, g_HAI);
    cudaGetSymbolAddress((void**)&H2p,  g_H2);
    cudaGetSymbolAddress((void**)&PRp,  g_PR);
    cudaGetSymbolAddress((void**)&WPp,  g_WP);
    cudaGetSymbolAddress((void**)&WPRp, g_WPRED);
    cudaGetSymbolAddress((void**)&WTCp, g_WTC);

    cudaFuncSetAttribute(node_tc, cudaFuncAttributeMaxDynamicSharedMemorySize, SMEM_TC);

    pack_kernel<<<(25600 + 255) / 256, 256>>>(fwh, fwi, ufw, uaw, h2o_w, WPp, WPRp);
    pack_wtc<<<(2560 + 127) / 128, 128>>>(awh, awi, WTCp);
    init_kernel<<<B / RB, NTHR>>>(z, z2h_w, z2h_b, H0p);

    EmitCtx P;
    P.wpred = WPRp; P.h2o_b = h2o_b;
    P.abi = abi; P.abh = abh; P.fbi = fbi; P.fbh = fbh;
    P.uab = uab; P.ufb = ufb;
    P.fwiP = WPp + OFF_WI_F; P.fwhP = WPp + OFF_WH_F;
    P.ufP  = WPp + OFF_UF;   P.uaP  = WPp + OFF_UA;
    P.WTC = WTCp;
    P.out = (float*)d_out;
    P.HAI = HAIp; P.H2 = H2p; P.PR = PRp;
    P.B = B; P.idx = 0;

    emit_node(P, 0, depth, H0p);
}